// round 1
// baseline (speedup 1.0000x reference)
#include <cuda_runtime.h>
#include <cuda_bf16.h>

#ifndef THR
#define THR 0.3f
#endif

// Each thread processes 4 rows:
//   loads  : 2 x float4  (8 floats  = 4 rows of (h, junk))
//   stores : 3 x float4  (12 floats = 4 rows x 3 outputs)
__global__ void __launch_bounds__(256) weighting_router_kernel(
    const float4* __restrict__ xin,   // N/2 float4 (each float4 = 2 rows)
    float4* __restrict__ out,         // 3N/4 float4
    int n_quads)                      // N/4
{
    int q = blockIdx.x * blockDim.x + threadIdx.x;
    if (q >= n_quads) return;

    // rows [4q, 4q+3]: input float4 index 2q and 2q+1
    float4 a = xin[2 * q];
    float4 b = xin[2 * q + 1];

    const float inv_hi = 1.0f / (1.0f - THR);  // 1/0.7
    const float inv_lo = 1.0f / THR;           // 1/0.3

    float h[4] = {a.x, a.z, b.x, b.z};
    float o[12];

#pragma unroll
    for (int i = 0; i < 4; i++) {
        float hv = h[i];
        bool hi = (hv >= THR);
        float c0 = hi ? (hv - THR) * inv_hi : 0.0f;
        float c1 = hi ? 0.0f : (THR - hv) * inv_lo;
        float c2 = hi ? (1.0f - hv) * inv_hi : hv * inv_lo;
        o[3 * i + 0] = c0;
        o[3 * i + 1] = c1;
        o[3 * i + 2] = c2;
    }

    float4* dst = out + 3 * q;
    dst[0] = make_float4(o[0], o[1], o[2],  o[3]);
    dst[1] = make_float4(o[4], o[5], o[6],  o[7]);
    dst[2] = make_float4(o[8], o[9], o[10], o[11]);
}

// Tail handler for rows not covered by the vectorized kernel (n % 4 != 0).
__global__ void weighting_router_tail(
    const float* __restrict__ x,
    float* __restrict__ out,
    int start_row, int n_rows)
{
    int i = start_row + blockIdx.x * blockDim.x + threadIdx.x;
    if (i >= n_rows) return;

    const float inv_hi = 1.0f / (1.0f - THR);
    const float inv_lo = 1.0f / THR;

    float hv = x[2 * i];
    bool hi = (hv >= THR);
    out[3 * i + 0] = hi ? (hv - THR) * inv_hi : 0.0f;
    out[3 * i + 1] = hi ? 0.0f : (THR - hv) * inv_lo;
    out[3 * i + 2] = hi ? (1.0f - hv) * inv_hi : hv * inv_lo;
}

extern "C" void kernel_launch(void* const* d_in, const int* in_sizes, int n_in,
                              void* d_out, int out_size)
{
    const float* x = (const float*)d_in[0];
    float* out = (float*)d_out;

    int n_rows = in_sizes[0] / 2;     // x is (N, 2)
    int n_quads = n_rows / 4;

    if (n_quads > 0) {
        int threads = 256;
        int blocks = (n_quads + threads - 1) / threads;
        weighting_router_kernel<<<blocks, threads>>>(
            (const float4*)x, (float4*)out, n_quads);
    }

    int done = n_quads * 4;
    int rem = n_rows - done;
    if (rem > 0) {
        int threads = 128;
        int blocks = (rem + threads - 1) / threads;
        weighting_router_tail<<<blocks, threads>>>(x, out, done, n_rows);
    }
}